// round 2
// baseline (speedup 1.0000x reference)
#include <cuda_runtime.h>
#include <cuda_bf16.h>
#include <math.h>

// Model dims
#define VOCAB 32000
#define DIM   1024
#define NH    16
#define NKV   4
#define FFD   4096
#define NL    8
#define HD    64
#define BATCH 2
#define SEQ   1024
#define NTOK  (BATCH*SEQ)   // 2048

// ---------------- scratch (device globals; no allocation allowed) ----------
__device__ float g_x[NTOK*DIM];
__device__ float g_h[NTOK*DIM];
__device__ float g_q[NTOK*DIM];
__device__ float g_k[NTOK*(NKV*HD)];
__device__ float g_v[NTOK*(NKV*HD)];
__device__ float g_ao[NTOK*DIM];
__device__ float g_gate[NTOK*FFD];
__device__ float g_up[NTOK*FFD];

// ---------------- embedding gather -----------------------------------------
__global__ void embed_k(const int* __restrict__ tok, const float* __restrict__ emb,
                        float* __restrict__ x) {
    int m = blockIdx.x;
    int t = tok[m];
    const float4* src = (const float4*)(emb + (size_t)t * DIM);
    float4* dst = (float4*)(x + (size_t)m * DIM);
    dst[threadIdx.x] = src[threadIdx.x];   // 256 threads * 4 floats = 1024
}

// ---------------- rmsnorm ---------------------------------------------------
__global__ void rmsnorm_k(const float* __restrict__ x, const float* __restrict__ w,
                          float* __restrict__ out) {
    int m = blockIdx.x;
    int tid = threadIdx.x;  // 256
    const float4* xr = (const float4*)(x + (size_t)m * DIM);
    float4 v = xr[tid];
    float ss = v.x*v.x + v.y*v.y + v.z*v.z + v.w*v.w;
    __shared__ float red[256];
    red[tid] = ss; __syncthreads();
    for (int s = 128; s > 0; s >>= 1) {
        if (tid < s) red[tid] += red[tid + s];
        __syncthreads();
    }
    float scale = rsqrtf(red[0] * (1.0f/DIM) + 1e-6f);
    float4 wv = ((const float4*)w)[tid];
    float4 o;
    o.x = v.x*scale*wv.x; o.y = v.y*scale*wv.y;
    o.z = v.z*scale*wv.z; o.w = v.w*scale*wv.w;
    ((float4*)(out + (size_t)m * DIM))[tid] = o;
}

// ---------------- SGEMM NN: C[M,N] = A[M,K] @ B[K,N] (+ add) ---------------
// BM=64 BN=64 BK=16, 128 threads, microtile 8x4. All dims multiples of tile.
#define BM 64
#define BN 64
#define BK 16
__global__ void __launch_bounds__(128) sgemm_nn(
        const float* __restrict__ A, const float* __restrict__ B,
        const float* __restrict__ add, float* __restrict__ C,
        int M, int N, int K) {
    __shared__ float As[BK][BM];
    __shared__ float Bs[BK][BN];
    int tid = threadIdx.x;
    int bm = blockIdx.y * BM;
    int bn = blockIdx.x * BN;
    int tx = tid & 15;      // 0..15 -> N
    int ty = tid >> 4;      // 0..7  -> M
    float acc[8][4];
    #pragma unroll
    for (int i = 0; i < 8; ++i)
        #pragma unroll
        for (int j = 0; j < 4; ++j) acc[i][j] = 0.f;

    for (int k0 = 0; k0 < K; k0 += BK) {
        #pragma unroll
        for (int i = 0; i < 2; ++i) {
            int idx = tid + i*128;          // 0..255
            int row = idx >> 2;              // 0..63
            int c4  = (idx & 3) << 2;        // 0,4,8,12
            float4 a = *(const float4*)(A + (size_t)(bm+row)*K + k0 + c4);
            As[c4+0][row] = a.x; As[c4+1][row] = a.y;
            As[c4+2][row] = a.z; As[c4+3][row] = a.w;
        }
        #pragma unroll
        for (int i = 0; i < 2; ++i) {
            int idx = tid + i*128;
            int row = idx >> 4;              // 0..15
            int c4  = (idx & 15) << 2;       // 0..60
            *(float4*)(&Bs[row][c4]) = *(const float4*)(B + (size_t)(k0+row)*N + bn + c4);
        }
        __syncthreads();
        #pragma unroll
        for (int k = 0; k < BK; ++k) {
            float ra[8], rb[4];
            *(float4*)(&ra[0]) = *(const float4*)(&As[k][ty*8]);
            *(float4*)(&ra[4]) = *(const float4*)(&As[k][ty*8+4]);
            *(float4*)(&rb[0]) = *(const float4*)(&Bs[k][tx*4]);
            #pragma unroll
            for (int i = 0; i < 8; ++i)
                #pragma unroll
                for (int j = 0; j < 4; ++j)
                    acc[i][j] = fmaf(ra[i], rb[j], acc[i][j]);
        }
        __syncthreads();
    }
    #pragma unroll
    for (int i = 0; i < 8; ++i) {
        int row = bm + ty*8 + i;
        int col = bn + tx*4;
        float4 o = make_float4(acc[i][0], acc[i][1], acc[i][2], acc[i][3]);
        if (add) {
            float4 r = *(const float4*)(add + (size_t)row*N + col);
            o.x += r.x; o.y += r.y; o.z += r.z; o.w += r.w;
        }
        *(float4*)(C + (size_t)row*N + col) = o;
    }
}

// ---------------- SGEMM NT: C[M,N] = A[M,K] @ E[N,K]^T (logits) ------------
__global__ void __launch_bounds__(128) sgemm_nt(
        const float* __restrict__ A, const float* __restrict__ E,
        float* __restrict__ C, int M, int N, int K) {
    __shared__ float As[BK][BM];
    __shared__ float Bs[BK][BN];
    int tid = threadIdx.x;
    int bm = blockIdx.y * BM;
    int bn = blockIdx.x * BN;
    int tx = tid & 15;
    int ty = tid >> 4;
    float acc[8][4];
    #pragma unroll
    for (int i = 0; i < 8; ++i)
        #pragma unroll
        for (int j = 0; j < 4; ++j) acc[i][j] = 0.f;

    for (int k0 = 0; k0 < K; k0 += BK) {
        #pragma unroll
        for (int i = 0; i < 2; ++i) {
            int idx = tid + i*128;
            int row = idx >> 2;
            int c4  = (idx & 3) << 2;
            float4 a = *(const float4*)(A + (size_t)(bm+row)*K + k0 + c4);
            As[c4+0][row] = a.x; As[c4+1][row] = a.y;
            As[c4+2][row] = a.z; As[c4+3][row] = a.w;
        }
        #pragma unroll
        for (int i = 0; i < 2; ++i) {
            int idx = tid + i*128;
            int n   = idx >> 2;              // 0..63
            int k4  = (idx & 3) << 2;        // 0,4,8,12
            float4 e = *(const float4*)(E + (size_t)(bn+n)*K + k0 + k4);
            Bs[k4+0][n] = e.x; Bs[k4+1][n] = e.y;
            Bs[k4+2][n] = e.z; Bs[k4+3][n] = e.w;
        }
        __syncthreads();
        #pragma unroll
        for (int k = 0; k < BK; ++k) {
            float ra[8], rb[4];
            *(float4*)(&ra[0]) = *(const float4*)(&As[k][ty*8]);
            *(float4*)(&ra[4]) = *(const float4*)(&As[k][ty*8+4]);
            *(float4*)(&rb[0]) = *(const float4*)(&Bs[k][tx*4]);
            #pragma unroll
            for (int i = 0; i < 8; ++i)
                #pragma unroll
                for (int j = 0; j < 4; ++j)
                    acc[i][j] = fmaf(ra[i], rb[j], acc[i][j]);
        }
        __syncthreads();
    }
    #pragma unroll
    for (int i = 0; i < 8; ++i) {
        int row = bm + ty*8 + i;
        int col = bn + tx*4;
        *(float4*)(C + (size_t)row*N + col) =
            make_float4(acc[i][0], acc[i][1], acc[i][2], acc[i][3]);
    }
}

// ---------------- RoPE (in-place) ------------------------------------------
// x: [NTOK, nh*HD]; grid (NTOK, nh); 32 threads (half-dim pairs)
__global__ void rope_k(float* __restrict__ x, int rowstride) {
    int m = blockIdx.x;
    int h = blockIdx.y;
    int s = m % SEQ;
    int j = threadIdx.x;  // 0..31
    float* p = x + (size_t)m * rowstride + h * HD;
    // inv_freq = 10000^(-2j/64) = exp(-(2j/64)*ln(10000))
    float invf = expf(-(2.0f * j / 64.0f) * 9.210340371976184f);
    float ang = (float)s * invf;
    float c, sn;
    sincosf(ang, &sn, &c);
    float x1 = p[j], x2 = p[j + 32];
    p[j]      = x1 * c - x2 * sn;
    p[j + 32] = x2 * c + x1 * sn;
}

// ---------------- attention: one block per (q, head, batch) ----------------
__global__ void __launch_bounds__(128) attn_k(
        const float* __restrict__ q, const float* __restrict__ k,
        const float* __restrict__ v, float* __restrict__ out) {
    int sq = blockIdx.x, h = blockIdx.y, b = blockIdx.z;
    int kvh = h >> 2;                       // NREP = 4
    int tid = threadIdx.x;                  // 128
    __shared__ float qs[HD];
    __shared__ float sc[SEQ];
    __shared__ float red[128];

    const float* qrow = q + ((size_t)(b*SEQ + sq)) * DIM + h * HD;
    if (tid < HD) qs[tid] = qrow[tid];
    __syncthreads();

    int nk = sq + 1;
    float lmax = -1e30f;
    for (int j = tid; j < nk; j += 128) {
        const float* kr = k + ((size_t)(b*SEQ + j)) * (NKV*HD) + kvh * HD;
        float d = 0.f;
        #pragma unroll
        for (int t = 0; t < 16; ++t) {
            float4 kk = *(const float4*)(kr + t*4);
            float4 qq = *(const float4*)(qs + t*4);
            d += kk.x*qq.x + kk.y*qq.y + kk.z*qq.z + kk.w*qq.w;
        }
        d *= 0.125f;                         // 1/sqrt(64)
        sc[j] = d;
        lmax = fmaxf(lmax, d);
    }
    red[tid] = lmax; __syncthreads();
    for (int s = 64; s > 0; s >>= 1) {
        if (tid < s) red[tid] = fmaxf(red[tid], red[tid + s]);
        __syncthreads();
    }
    float mx = red[0];
    __syncthreads();

    float lsum = 0.f;
    for (int j = tid; j < nk; j += 128) {
        float p = expf(sc[j] - mx);
        sc[j] = p;
        lsum += p;
    }
    red[tid] = lsum; __syncthreads();
    for (int s = 64; s > 0; s >>= 1) {
        if (tid < s) red[tid] += red[tid + s];
        __syncthreads();
    }
    float inv = 1.0f / red[0];
    __syncthreads();

    // out accumulation: thread -> (dim d, half part)
    int d = tid & 63, part = tid >> 6;
    float acc = 0.f;
    for (int j = part; j < nk; j += 2) {
        acc += sc[j] * v[((size_t)(b*SEQ + j)) * (NKV*HD) + kvh * HD + d];
    }
    red[tid] = acc; __syncthreads();
    if (tid < 64)
        out[((size_t)(b*SEQ + sq)) * DIM + h * HD + tid] = (red[tid] + red[tid + 64]) * inv;
}

// ---------------- silu(gate) * up -> gate ----------------------------------
__global__ void silu_mul_k(float* __restrict__ gate, const float* __restrict__ up, int n) {
    int i = blockIdx.x * 256 + threadIdx.x;
    if (i < n) {
        float g = gate[i];
        gate[i] = (g / (1.0f + expf(-g))) * up[i];
    }
}

// ---------------- host orchestration ---------------------------------------
extern "C" void kernel_launch(void* const* d_in, const int* in_sizes, int n_in,
                              void* d_out, int out_size) {
    const int*   tokens  = (const int*)  d_in[0];
    const float* embed   = (const float*)d_in[1];
    const float* wq      = (const float*)d_in[2];
    const float* wk      = (const float*)d_in[3];
    const float* wv      = (const float*)d_in[4];
    const float* wo      = (const float*)d_in[5];
    const float* w_gate  = (const float*)d_in[6];
    const float* w_up    = (const float*)d_in[7];
    const float* w_down  = (const float*)d_in[8];
    const float* norm1_w = (const float*)d_in[9];
    const float* norm2_w = (const float*)d_in[10];
    const float* fnorm_w = (const float*)d_in[11];
    float* logits = (float*)d_out;

    float *x, *h, *q, *k, *v, *ao, *gate, *up;
    cudaGetSymbolAddress((void**)&x,    g_x);
    cudaGetSymbolAddress((void**)&h,    g_h);
    cudaGetSymbolAddress((void**)&q,    g_q);
    cudaGetSymbolAddress((void**)&k,    g_k);
    cudaGetSymbolAddress((void**)&v,    g_v);
    cudaGetSymbolAddress((void**)&ao,   g_ao);
    cudaGetSymbolAddress((void**)&gate, g_gate);
    cudaGetSymbolAddress((void**)&up,   g_up);

    dim3 g_d(DIM/BN,   NTOK/BM);     // (16, 32)
    dim3 g_kv((NKV*HD)/BN, NTOK/BM); // (4, 32)
    dim3 g_ff(FFD/BN,  NTOK/BM);     // (64, 32)
    dim3 g_lg(VOCAB/BN, NTOK/BM);    // (500, 32)

    embed_k<<<NTOK, 256>>>(tokens, embed, x);

    for (int i = 0; i < NL; ++i) {
        const float* wqi = wq + (size_t)i * DIM * (NH*HD);
        const float* wki = wk + (size_t)i * DIM * (NKV*HD);
        const float* wvi = wv + (size_t)i * DIM * (NKV*HD);
        const float* woi = wo + (size_t)i * (NH*HD) * DIM;
        const float* wgi = w_gate + (size_t)i * DIM * FFD;
        const float* wui = w_up   + (size_t)i * DIM * FFD;
        const float* wdi = w_down + (size_t)i * FFD * DIM;

        rmsnorm_k<<<NTOK, 256>>>(x, norm1_w + (size_t)i*DIM, h);

        sgemm_nn<<<g_d, 128>>>(h, wqi, nullptr, q, NTOK, DIM, DIM);
        sgemm_nn<<<g_kv, 128>>>(h, wki, nullptr, k, NTOK, NKV*HD, DIM);
        sgemm_nn<<<g_kv, 128>>>(h, wvi, nullptr, v, NTOK, NKV*HD, DIM);

        rope_k<<<dim3(NTOK, NH), 32>>>(q, DIM);
        rope_k<<<dim3(NTOK, NKV), 32>>>(k, NKV*HD);

        attn_k<<<dim3(SEQ, NH, BATCH), 128>>>(q, k, v, ao);

        sgemm_nn<<<g_d, 128>>>(ao, woi, x, x, NTOK, DIM, DIM);

        rmsnorm_k<<<NTOK, 256>>>(x, norm2_w + (size_t)i*DIM, h);

        sgemm_nn<<<g_ff, 128>>>(h, wgi, nullptr, gate, NTOK, FFD, DIM);
        sgemm_nn<<<g_ff, 128>>>(h, wui, nullptr, up,   NTOK, FFD, DIM);

        silu_mul_k<<<(NTOK*FFD)/256, 256>>>(gate, up, NTOK*FFD);

        sgemm_nn<<<g_d, 128>>>(gate, wdi, x, x, NTOK, DIM, FFD);
    }

    rmsnorm_k<<<NTOK, 256>>>(x, fnorm_w, h);
    sgemm_nt<<<g_lg, 128>>>(h, embed, logits, NTOK, VOCAB, DIM);
}

// round 5
// speedup vs baseline: 1.1973x; 1.1973x over previous
#include <cuda_runtime.h>
#include <cuda_bf16.h>
#include <math.h>
#include <stdint.h>

// Model dims
#define VOCAB 32000
#define DIM   1024
#define NH    16
#define NKV   4
#define FFD   4096
#define NL    8
#define HD    64
#define BATCH 2
#define SEQ   1024
#define NTOK  (BATCH*SEQ)   // 2048

// ---------------- scratch (device globals; no allocation allowed) ----------
__device__ float g_x[NTOK*DIM];
__device__ float g_h[NTOK*DIM];
__device__ float g_q[NTOK*DIM];
__device__ float g_k[NTOK*(NKV*HD)];
__device__ float g_v[NTOK*(NKV*HD)];
__device__ float g_ao[NTOK*DIM];
__device__ float g_gate[NTOK*FFD];
__device__ float g_up[NTOK*FFD];

// ---------------- small helpers --------------------------------------------
__device__ __forceinline__ uint32_t f2tf(float x) {
    uint32_t r;
    asm("cvt.rna.tf32.f32 %0, %1;" : "=r"(r) : "f"(x));
    return r;
}
// split x into hi (tf32) + lo (tf32 of remainder): 3xTF32 trick
__device__ __forceinline__ void split_tf(float x, uint32_t& hi, uint32_t& lo) {
    hi = f2tf(x);
    lo = f2tf(x - __uint_as_float(hi));
}

#define CP16(dst, src) asm volatile("cp.async.cg.shared.global [%0], [%1], 16;\n" :: "r"(dst), "l"(src))
#define CP_COMMIT()    asm volatile("cp.async.commit_group;\n")
#define CP_WAIT0()     asm volatile("cp.async.wait_group 0;\n")

__device__ __forceinline__ void mma_tf32(float c[4], const uint32_t a[4], const uint32_t b[2]) {
    asm volatile(
        "mma.sync.aligned.m16n8k8.row.col.f32.tf32.tf32.f32 "
        "{%0,%1,%2,%3}, {%4,%5,%6,%7}, {%8,%9}, {%0,%1,%2,%3};\n"
        : "+f"(c[0]), "+f"(c[1]), "+f"(c[2]), "+f"(c[3])
        : "r"(a[0]), "r"(a[1]), "r"(a[2]), "r"(a[3]), "r"(b[0]), "r"(b[1]));
}

// ---------------- embedding gather -----------------------------------------
__global__ void embed_k(const int* __restrict__ tok, const float* __restrict__ emb,
                        float* __restrict__ x) {
    int m = blockIdx.x;
    int t = tok[m];
    const float4* src = (const float4*)(emb + (size_t)t * DIM);
    float4* dst = (float4*)(x + (size_t)m * DIM);
    dst[threadIdx.x] = src[threadIdx.x];
}

// ---------------- rmsnorm ---------------------------------------------------
__global__ void rmsnorm_k(const float* __restrict__ x, const float* __restrict__ w,
                          float* __restrict__ out) {
    int m = blockIdx.x;
    int tid = threadIdx.x;  // 256
    const float4* xr = (const float4*)(x + (size_t)m * DIM);
    float4 v = xr[tid];
    float ss = v.x*v.x + v.y*v.y + v.z*v.z + v.w*v.w;
    __shared__ float red[256];
    red[tid] = ss; __syncthreads();
    for (int s = 128; s > 0; s >>= 1) {
        if (tid < s) red[tid] += red[tid + s];
        __syncthreads();
    }
    float scale = rsqrtf(red[0] * (1.0f/DIM) + 1e-6f);
    float4 wv = ((const float4*)w)[tid];
    float4 o;
    o.x = v.x*scale*wv.x; o.y = v.y*scale*wv.y;
    o.z = v.z*scale*wv.z; o.w = v.w*scale*wv.w;
    ((float4*)(out + (size_t)m * DIM))[tid] = o;
}

// ============================================================================
// 3xTF32 tensor-core GEMM (NN): C[M,N] = A[M,K] @ B[K,N] (+ add)
// BM=128 BN=128 BK=16, 256 threads (8 warps: 4 along M x 2 along N),
// warp tile 32x64 = 2x8 m16n8k8 atoms. cp.async 2-stage pipeline.
// Each operand split hi/lo in tf32; accumulate ah*bh + al*bh + ah*bl.
// ============================================================================
#define GBM 128
#define GBN 128
#define GBK 16
#define AST 20      // As row stride (floats)
#define BST 136     // Bs row stride (floats)
#define A_STAGE_B (GBM*AST*4)  // 10240 bytes
#define B_STAGE_B (GBK*BST*4)  // 8704 bytes

__global__ void __launch_bounds__(256) gemm_tc_nn(
        const float* __restrict__ A, const float* __restrict__ B,
        const float* __restrict__ add, float* __restrict__ C,
        int M, int N, int K) {
    __shared__ float As[2][GBM][AST];
    __shared__ float Bs[2][GBK][BST];

    int tid = threadIdx.x;
    int bm = blockIdx.y * GBM;
    int bn = blockIdx.x * GBN;
    int w = tid >> 5, lane = tid & 31;
    int wm = w & 3, wn = w >> 2;            // warp coords: 4 x 2
    int g = lane >> 2, tig = lane & 3;

    float c[2][8][4];
    #pragma unroll
    for (int i = 0; i < 2; ++i)
        #pragma unroll
        for (int j = 0; j < 8; ++j)
            #pragma unroll
            for (int q = 0; q < 4; ++q) c[i][j][q] = 0.f;

    uint32_t asBase = (uint32_t)__cvta_generic_to_shared(&As[0][0][0]);
    uint32_t bsBase = (uint32_t)__cvta_generic_to_shared(&Bs[0][0][0]);
    int arow = tid >> 2, ak4 = (tid & 3) << 2;      // A: rows 0..63 (+64), k4
    int brow = tid >> 5, bn4 = (tid & 31) << 2;     // B: rows 0..7 (+8), n4
    uint32_t aDst0 = asBase + (uint32_t)(arow*AST + ak4) * 4;
    uint32_t aDst1 = aDst0 + (uint32_t)(64*AST*4);
    uint32_t bDst0 = bsBase + (uint32_t)(brow*BST + bn4) * 4;
    uint32_t bDst1 = bDst0 + (uint32_t)(8*BST*4);

    const float* aSrc = A + (size_t)(bm + arow) * K + ak4;
    const float* bSrc = B + (size_t)brow * N + bn + bn4;

    int ntiles = K / GBK;

    // prologue: stage 0
    CP16(aDst0, aSrc);
    CP16(aDst1, aSrc + (size_t)64 * K);
    CP16(bDst0, bSrc);
    CP16(bDst1, bSrc + (size_t)8 * N);
    CP_COMMIT();

    for (int t = 0; t < ntiles; ++t) {
        CP_WAIT0();
        __syncthreads();

        if (t + 1 < ntiles) {
            int s = (t + 1) & 1;
            int k0 = (t + 1) * GBK;
            const float* ap = aSrc + k0;
            const float* bp = bSrc + (size_t)k0 * N;
            CP16(aDst0 + s*A_STAGE_B, ap);
            CP16(aDst1 + s*A_STAGE_B, ap + (size_t)64 * K);
            CP16(bDst0 + s*B_STAGE_B, bp);
            CP16(bDst1 + s*B_STAGE_B, bp + (size_t)8 * N);
            CP_COMMIT();
        }

        int s = t & 1;
        #pragma unroll
        for (int kk = 0; kk < GBK; kk += 8) {
            uint32_t ah[2][4], al[2][4], bh[8][2], bl[8][2];
            #pragma unroll
            for (int ma = 0; ma < 2; ++ma) {
                int r = wm*32 + ma*16 + g;
                split_tf(As[s][r    ][kk + tig    ], ah[ma][0], al[ma][0]);
                split_tf(As[s][r + 8][kk + tig    ], ah[ma][1], al[ma][1]);
                split_tf(As[s][r    ][kk + tig + 4], ah[ma][2], al[ma][2]);
                split_tf(As[s][r + 8][kk + tig + 4], ah[ma][3], al[ma][3]);
            }
            #pragma unroll
            for (int nb = 0; nb < 8; ++nb) {
                int col = wn*64 + nb*8 + g;
                split_tf(Bs[s][kk + tig    ][col], bh[nb][0], bl[nb][0]);
                split_tf(Bs[s][kk + tig + 4][col], bh[nb][1], bl[nb][1]);
            }
            #pragma unroll
            for (int ma = 0; ma < 2; ++ma)
                #pragma unroll
                for (int nb = 0; nb < 8; ++nb) {
                    mma_tf32(c[ma][nb], ah[ma], bh[nb]);
                    mma_tf32(c[ma][nb], al[ma], bh[nb]);
                    mma_tf32(c[ma][nb], ah[ma], bl[nb]);
                }
        }
        __syncthreads();
    }

    // epilogue
    #pragma unroll
    for (int ma = 0; ma < 2; ++ma) {
        int r0 = bm + wm*32 + ma*16 + g;
        int r1 = r0 + 8;
        #pragma unroll
        for (int nb = 0; nb < 8; ++nb) {
            int col = bn + wn*64 + nb*8 + tig*2;
            float2 o0 = make_float2(c[ma][nb][0], c[ma][nb][1]);
            float2 o1 = make_float2(c[ma][nb][2], c[ma][nb][3]);
            if (add) {
                float2 r;
                r = *(const float2*)(add + (size_t)r0*N + col);
                o0.x += r.x; o0.y += r.y;
                r = *(const float2*)(add + (size_t)r1*N + col);
                o1.x += r.x; o1.y += r.y;
            }
            *(float2*)(C + (size_t)r0*N + col) = o0;
            *(float2*)(C + (size_t)r1*N + col) = o1;
        }
    }
}

// ============================================================================
// 3xTF32 tensor-core GEMM (NT): C[M,N] = A[M,K] @ E[N,K]^T   (logits)
// ============================================================================
__global__ void __launch_bounds__(256) gemm_tc_nt(
        const float* __restrict__ A, const float* __restrict__ E,
        float* __restrict__ C, int M, int N, int K) {
    __shared__ float As[GBM][AST];
    __shared__ float Bs[GBK][BST];

    int tid = threadIdx.x;
    int bm = blockIdx.y * GBM;
    int bn = blockIdx.x * GBN;
    int w = tid >> 5, lane = tid & 31;
    int wm = w & 3, wn = w >> 2;
    int g = lane >> 2, tig = lane & 3;

    float c[2][8][4];
    #pragma unroll
    for (int i = 0; i < 2; ++i)
        #pragma unroll
        for (int j = 0; j < 8; ++j)
            #pragma unroll
            for (int q = 0; q < 4; ++q) c[i][j][q] = 0.f;

    int arow = tid >> 2, ak4 = (tid & 3) << 2;   // A rows 0..63 (+64)
    int nrow = tid >> 2, nk4 = (tid & 3) << 2;   // E rows (n) 0..63 (+64)

    for (int k0 = 0; k0 < K; k0 += GBK) {
        __syncthreads();
        // A tile
        #pragma unroll
        for (int i = 0; i < 2; ++i) {
            int r = arow + i*64;
            float4 a = *(const float4*)(A + (size_t)(bm + r)*K + k0 + ak4);
            *(float4*)(&As[r][ak4]) = a;
        }
        // B tile (transpose E[n][k] -> Bs[k][n])
        #pragma unroll
        for (int i = 0; i < 2; ++i) {
            int n = nrow + i*64;
            float4 e = *(const float4*)(E + (size_t)(bn + n)*K + k0 + nk4);
            Bs[nk4+0][n] = e.x; Bs[nk4+1][n] = e.y;
            Bs[nk4+2][n] = e.z; Bs[nk4+3][n] = e.w;
        }
        __syncthreads();

        #pragma unroll
        for (int kk = 0; kk < GBK; kk += 8) {
            uint32_t ah[2][4], al[2][4], bh[8][2], bl[8][2];
            #pragma unroll
            for (int ma = 0; ma < 2; ++ma) {
                int r = wm*32 + ma*16 + g;
                split_tf(As[r    ][kk + tig    ], ah[ma][0], al[ma][0]);
                split_tf(As[r + 8][kk + tig    ], ah[ma][1], al[ma][1]);
                split_tf(As[r    ][kk + tig + 4], ah[ma][2], al[ma][2]);
                split_tf(As[r + 8][kk + tig + 4], ah[ma][3], al[ma][3]);
            }
            #pragma unroll
            for (int nb = 0; nb < 8; ++nb) {
                int col = wn*64 + nb*8 + g;
                split_tf(Bs[kk + tig    ][col], bh[nb][0], bl[nb][0]);
                split_tf(Bs[kk + tig + 4][col], bh[nb][1], bl[nb][1]);
            }
            #pragma unroll
            for (int ma = 0; ma < 2; ++ma)
                #pragma unroll
                for (int nb = 0; nb < 8; ++nb) {
                    mma_tf32(c[ma][nb], ah[ma], bh[nb]);
                    mma_tf32(c[ma][nb], al[ma], bh[nb]);
                    mma_tf32(c[ma][nb], ah[ma], bl[nb]);
                }
        }
    }

    #pragma unroll
    for (int ma = 0; ma < 2; ++ma) {
        int r0 = bm + wm*32 + ma*16 + g;
        int r1 = r0 + 8;
        #pragma unroll
        for (int nb = 0; nb < 8; ++nb) {
            int col = bn + wn*64 + nb*8 + tig*2;
            *(float2*)(C + (size_t)r0*N + col) = make_float2(c[ma][nb][0], c[ma][nb][1]);
            *(float2*)(C + (size_t)r1*N + col) = make_float2(c[ma][nb][2], c[ma][nb][3]);
        }
    }
}

// ---------------- RoPE (in-place) ------------------------------------------
__global__ void rope_k(float* __restrict__ x, int rowstride) {
    int m = blockIdx.x;
    int h = blockIdx.y;
    int s = m % SEQ;
    int j = threadIdx.x;  // 0..31
    float* p = x + (size_t)m * rowstride + h * HD;
    float invf = expf(-(2.0f * j / 64.0f) * 9.210340371976184f);
    float ang = (float)s * invf;
    float cc, sn;
    sincosf(ang, &sn, &cc);
    float x1 = p[j], x2 = p[j + 32];
    p[j]      = x1 * cc - x2 * sn;
    p[j + 32] = x2 * cc + x1 * sn;
}

// ---------------- attention: one block per (q, head, batch) ----------------
__global__ void __launch_bounds__(128) attn_k(
        const float* __restrict__ q, const float* __restrict__ k,
        const float* __restrict__ v, float* __restrict__ out) {
    int sq = blockIdx.x, h = blockIdx.y, b = blockIdx.z;
    int kvh = h >> 2;                       // NREP = 4
    int tid = threadIdx.x;                  // 128
    __shared__ float qs[HD];
    __shared__ float sc[SEQ];
    __shared__ float red[128];

    const float* qrow = q + ((size_t)(b*SEQ + sq)) * DIM + h * HD;
    if (tid < HD) qs[tid] = qrow[tid];
    __syncthreads();

    int nk = sq + 1;
    float lmax = -1e30f;
    for (int j = tid; j < nk; j += 128) {
        const float* kr = k + ((size_t)(b*SEQ + j)) * (NKV*HD) + kvh * HD;
        float d = 0.f;
        #pragma unroll
        for (int t = 0; t < 16; ++t) {
            float4 kk = *(const float4*)(kr + t*4);
            float4 qq = *(const float4*)(qs + t*4);
            d += kk.x*qq.x + kk.y*qq.y + kk.z*qq.z + kk.w*qq.w;
        }
        d *= 0.125f;
        sc[j] = d;
        lmax = fmaxf(lmax, d);
    }
    red[tid] = lmax; __syncthreads();
    for (int s = 64; s > 0; s >>= 1) {
        if (tid < s) red[tid] = fmaxf(red[tid], red[tid + s]);
        __syncthreads();
    }
    float mx = red[0];
    __syncthreads();

    float lsum = 0.f;
    for (int j = tid; j < nk; j += 128) {
        float p = expf(sc[j] - mx);
        sc[j] = p;
        lsum += p;
    }
    red[tid] = lsum; __syncthreads();
    for (int s = 64; s > 0; s >>= 1) {
        if (tid < s) red[tid] += red[tid + s];
        __syncthreads();
    }
    float inv = 1.0f / red[0];
    __syncthreads();

    int d = tid & 63, part = tid >> 6;
    float acc = 0.f;
    for (int j = part; j < nk; j += 2) {
        acc += sc[j] * v[((size_t)(b*SEQ + j)) * (NKV*HD) + kvh * HD + d];
    }
    red[tid] = acc; __syncthreads();
    if (tid < 64)
        out[((size_t)(b*SEQ + sq)) * DIM + h * HD + tid] = (red[tid] + red[tid + 64]) * inv;
}

// ---------------- silu(gate) * up -> gate ----------------------------------
__global__ void silu_mul_k(float* __restrict__ gate, const float* __restrict__ up, int n) {
    int i = blockIdx.x * 256 + threadIdx.x;
    if (i < n) {
        float g = gate[i];
        gate[i] = (g / (1.0f + expf(-g))) * up[i];
    }
}

// ---------------- host orchestration ---------------------------------------
extern "C" void kernel_launch(void* const* d_in, const int* in_sizes, int n_in,
                              void* d_out, int out_size) {
    const int*   tokens  = (const int*)  d_in[0];
    const float* embed   = (const float*)d_in[1];
    const float* wq      = (const float*)d_in[2];
    const float* wk      = (const float*)d_in[3];
    const float* wv      = (const float*)d_in[4];
    const float* wo      = (const float*)d_in[5];
    const float* w_gate  = (const float*)d_in[6];
    const float* w_up    = (const float*)d_in[7];
    const float* w_down  = (const float*)d_in[8];
    const float* norm1_w = (const float*)d_in[9];
    const float* norm2_w = (const float*)d_in[10];
    const float* fnorm_w = (const float*)d_in[11];
    float* logits = (float*)d_out;

    float *x, *h, *q, *k, *v, *ao, *gate, *up;
    cudaGetSymbolAddress((void**)&x,    g_x);
    cudaGetSymbolAddress((void**)&h,    g_h);
    cudaGetSymbolAddress((void**)&q,    g_q);
    cudaGetSymbolAddress((void**)&k,    g_k);
    cudaGetSymbolAddress((void**)&v,    g_v);
    cudaGetSymbolAddress((void**)&ao,   g_ao);
    cudaGetSymbolAddress((void**)&gate, g_gate);
    cudaGetSymbolAddress((void**)&up,   g_up);

    dim3 g_d(DIM/GBN,      NTOK/GBM);   // (8, 16)
    dim3 g_kv((NKV*HD)/GBN, NTOK/GBM);  // (2, 16)
    dim3 g_ff(FFD/GBN,     NTOK/GBM);   // (32, 16)
    dim3 g_lg(VOCAB/GBN,   NTOK/GBM);   // (250, 16)

    embed_k<<<NTOK, 256>>>(tokens, embed, x);

    for (int i = 0; i < NL; ++i) {
        const float* wqi = wq + (size_t)i * DIM * (NH*HD);
        const float* wki = wk + (size_t)i * DIM * (NKV*HD);
        const float* wvi = wv + (size_t)i * DIM * (NKV*HD);
        const float* woi = wo + (size_t)i * (NH*HD) * DIM;
        const float* wgi = w_gate + (size_t)i * DIM * FFD;
        const float* wui = w_up   + (size_t)i * DIM * FFD;
        const float* wdi = w_down + (size_t)i * FFD * DIM;

        rmsnorm_k<<<NTOK, 256>>>(x, norm1_w + (size_t)i*DIM, h);

        gemm_tc_nn<<<g_d,  256>>>(h, wqi, nullptr, q, NTOK, DIM, DIM);
        gemm_tc_nn<<<g_kv, 256>>>(h, wki, nullptr, k, NTOK, NKV*HD, DIM);
        gemm_tc_nn<<<g_kv, 256>>>(h, wvi, nullptr, v, NTOK, NKV*HD, DIM);

        rope_k<<<dim3(NTOK, NH), 32>>>(q, DIM);
        rope_k<<<dim3(NTOK, NKV), 32>>>(k, NKV*HD);

        attn_k<<<dim3(SEQ, NH, BATCH), 128>>>(q, k, v, ao);

        gemm_tc_nn<<<g_d, 256>>>(ao, woi, x, x, NTOK, DIM, DIM);

        rmsnorm_k<<<NTOK, 256>>>(x, norm2_w + (size_t)i*DIM, h);

        gemm_tc_nn<<<g_ff, 256>>>(h, wgi, nullptr, gate, NTOK, FFD, DIM);
        gemm_tc_nn<<<g_ff, 256>>>(h, wui, nullptr, up,   NTOK, FFD, DIM);

        silu_mul_k<<<(NTOK*FFD)/256, 256>>>(gate, up, NTOK*FFD);

        gemm_tc_nn<<<g_d, 256>>>(gate, wdi, x, x, NTOK, DIM, FFD);
    }

    rmsnorm_k<<<NTOK, 256>>>(x, fnorm_w, h);
    gemm_tc_nt<<<g_lg, 256>>>(h, embed, logits, NTOK, VOCAB, DIM);
}

// round 6
// speedup vs baseline: 1.5563x; 1.2999x over previous
#include <cuda_runtime.h>
#include <cuda_bf16.h>
#include <math.h>
#include <stdint.h>

// Model dims
#define VOCAB 32000
#define DIM   1024
#define NH    16
#define NKV   4
#define FFD   4096
#define NL    8
#define HD    64
#define BATCH 2
#define SEQ   1024
#define NTOK  (BATCH*SEQ)   // 2048
#define QKVN  1536          // 1024 q + 256 k + 256 v
#define GUN   8192          // gate | up

// ---------------- scratch (device globals; no allocation allowed) ----------
__device__ float g_x[NTOK*DIM];
__device__ float g_qkv[NTOK*QKVN];
__device__ float g_ao[NTOK*DIM];
__device__ float g_gu[NTOK*GUN];

// split activations (packed bf16 hi/lo pairs along k; u32 per pair)
__device__ uint32_t g_hh[NTOK*DIM/2],  g_hl[NTOK*DIM/2];
__device__ uint32_t g_aoh[NTOK*DIM/2], g_aol[NTOK*DIM/2];
__device__ uint32_t g_ffh[NTOK*FFD/2], g_ffl[NTOK*FFD/2];

// split weights (B layout: [k2][n], pair along k)
__device__ uint32_t g_wqkvh[NL*(DIM/2)*QKVN], g_wqkvl[NL*(DIM/2)*QKVN];
__device__ uint32_t g_woh[NL*(DIM/2)*DIM],    g_wol[NL*(DIM/2)*DIM];
__device__ uint32_t g_wguh[NL*(DIM/2)*GUN],   g_wgul[NL*(DIM/2)*GUN];
__device__ uint32_t g_wdh[NL*(FFD/2)*DIM],    g_wdl[NL*(FFD/2)*DIM];
// split embed (A layout: [n][k2], pair along k contiguous)
__device__ uint32_t g_embh[VOCAB*(DIM/2)], g_embl[VOCAB*(DIM/2)];

// ---------------- helpers ---------------------------------------------------
__device__ __forceinline__ void split2(float x0, float x1, uint32_t& hi, uint32_t& lo) {
    __nv_bfloat16 h0 = __float2bfloat16_rn(x0);
    __nv_bfloat16 h1 = __float2bfloat16_rn(x1);
    __nv_bfloat16 l0 = __float2bfloat16_rn(x0 - __bfloat162float(h0));
    __nv_bfloat16 l1 = __float2bfloat16_rn(x1 - __bfloat162float(h1));
    hi = ((uint32_t)__bfloat16_as_ushort(h1) << 16) | __bfloat16_as_ushort(h0);
    lo = ((uint32_t)__bfloat16_as_ushort(l1) << 16) | __bfloat16_as_ushort(l0);
}

#define CP16(dst, src) asm volatile("cp.async.cg.shared.global [%0], [%1], 16;\n" :: "r"(dst), "l"(src))
#define CP_COMMIT()    asm volatile("cp.async.commit_group;\n")
#define CP_WAIT0()     asm volatile("cp.async.wait_group 0;\n")

__device__ __forceinline__ void mma_bf16(float c[4], const uint32_t a[4], const uint32_t b[2]) {
    asm volatile(
        "mma.sync.aligned.m16n8k16.row.col.f32.bf16.bf16.f32 "
        "{%0,%1,%2,%3}, {%4,%5,%6,%7}, {%8,%9}, {%0,%1,%2,%3};\n"
        : "+f"(c[0]), "+f"(c[1]), "+f"(c[2]), "+f"(c[3])
        : "r"(a[0]), "r"(a[1]), "r"(a[2]), "r"(a[3]), "r"(b[0]), "r"(b[1]));
}

// ---------------- weight split kernels --------------------------------------
// B layout: dst[k2][ldDst] = pack(src[2k2][n], src[2k2+1][n])
__global__ void split_B(const float* __restrict__ src, uint32_t* __restrict__ dh,
                        uint32_t* __restrict__ dl, int K2, int N, int ldDst) {
    int idx = blockIdx.x * 256 + threadIdx.x;
    if (idx >= K2 * N) return;
    int k2 = idx / N, n = idx - k2 * N;
    float x0 = src[(size_t)(2*k2)   * N + n];
    float x1 = src[(size_t)(2*k2+1) * N + n];
    uint32_t hi, lo;
    split2(x0, x1, hi, lo);
    dh[(size_t)k2 * ldDst + n] = hi;
    dl[(size_t)k2 * ldDst + n] = lo;
}

// A layout: dst[i] = pack(src[2i], src[2i+1])  (contiguous)
__global__ void split_A(const float* __restrict__ src, uint32_t* __restrict__ dh,
                        uint32_t* __restrict__ dl, int n2) {
    int i = blockIdx.x * 256 + threadIdx.x;
    if (i >= n2) return;
    float2 x = ((const float2*)src)[i];
    uint32_t hi, lo;
    split2(x.x, x.y, hi, lo);
    dh[i] = hi; dl[i] = lo;
}

// ---------------- embedding gather ------------------------------------------
__global__ void embed_k(const int* __restrict__ tok, const float* __restrict__ emb,
                        float* __restrict__ x) {
    int m = blockIdx.x;
    int t = tok[m];
    const float4* src = (const float4*)(emb + (size_t)t * DIM);
    float4* dst = (float4*)(x + (size_t)m * DIM);
    dst[threadIdx.x] = src[threadIdx.x];
}

// ---------------- rmsnorm -> split bf16 hi/lo -------------------------------
__global__ void rmsnorm_split_k(const float* __restrict__ x, const float* __restrict__ w,
                                uint32_t* __restrict__ dh, uint32_t* __restrict__ dl) {
    int m = blockIdx.x;
    int tid = threadIdx.x;  // 256
    const float4* xr = (const float4*)(x + (size_t)m * DIM);
    float4 v = xr[tid];
    float ss = v.x*v.x + v.y*v.y + v.z*v.z + v.w*v.w;
    __shared__ float red[256];
    red[tid] = ss; __syncthreads();
    for (int s = 128; s > 0; s >>= 1) {
        if (tid < s) red[tid] += red[tid + s];
        __syncthreads();
    }
    float scale = rsqrtf(red[0] * (1.0f/DIM) + 1e-6f);
    float4 wv = ((const float4*)w)[tid];
    float o0 = v.x*scale*wv.x, o1 = v.y*scale*wv.y;
    float o2 = v.z*scale*wv.z, o3 = v.w*scale*wv.w;
    uint32_t h0, l0, h1, l1;
    split2(o0, o1, h0, l0);
    split2(o2, o3, h1, l1);
    size_t base = (size_t)m * (DIM/2) + tid*2;
    dh[base] = h0; dh[base+1] = h1;
    dl[base] = l0; dl[base+1] = l1;
}

// ============================================================================
// 3xBF16 tensor-core GEMM (NN): C[M,N] = A[M,K] @ B[K,N] (+ add)
// A pre-split: Ah/Al [M][K2] u32 (pair along k). B pre-split: Bh/Bl [K2][N].
// BM=128 BN=128 BK=16 (K2T=8), 256 threads, 8 warps (4M x 2N), warp 32x64.
// cp.async 2-stage pipeline. 3 MMAs per atom: ah*bh + al*bh + ah*bl.
// ============================================================================
#define K2T 8
#define ASTP 12     // A smem row stride (u32)
#define BSTP 132    // B smem row stride (u32)

__global__ void __launch_bounds__(256) gemm3bf_nn(
        const uint32_t* __restrict__ Ah, const uint32_t* __restrict__ Al,
        const uint32_t* __restrict__ Bh, const uint32_t* __restrict__ Bl,
        const float* __restrict__ add, float* __restrict__ C,
        int M, int N, int K2) {
    __shared__ uint32_t sAh[2][128][ASTP], sAl[2][128][ASTP];
    __shared__ uint32_t sBh[2][K2T][BSTP], sBl[2][K2T][BSTP];

    int tid = threadIdx.x;
    int bm = blockIdx.y * 128;
    int bn = blockIdx.x * 128;
    int w = tid >> 5, lane = tid & 31;
    int wm = w & 3, wn = w >> 2;
    int g = lane >> 2, tig = lane & 3;

    float c[2][8][4];
    #pragma unroll
    for (int i = 0; i < 2; ++i)
        #pragma unroll
        for (int j = 0; j < 8; ++j)
            #pragma unroll
            for (int q = 0; q < 4; ++q) c[i][j][q] = 0.f;

    // loader mapping
    int arow = tid >> 1, ahalf = (tid & 1) * 4;   // A: row 0..127, k2-half
    int brow = tid >> 5, bn4 = (lane) * 4;        // B: row 0..7, 4 n's
    uint32_t aHiDst = (uint32_t)__cvta_generic_to_shared(&sAh[0][arow][ahalf]);
    uint32_t aLoDst = (uint32_t)__cvta_generic_to_shared(&sAl[0][arow][ahalf]);
    uint32_t bHiDst = (uint32_t)__cvta_generic_to_shared(&sBh[0][brow][bn4]);
    uint32_t bLoDst = (uint32_t)__cvta_generic_to_shared(&sBl[0][brow][bn4]);
    const uint32_t AS = 128*ASTP*4;   // stage stride bytes (A)
    const uint32_t BS = K2T*BSTP*4;   // stage stride bytes (B)

    const uint32_t* aHiSrc = Ah + (size_t)(bm + arow) * K2 + ahalf;
    const uint32_t* aLoSrc = Al + (size_t)(bm + arow) * K2 + ahalf;
    const uint32_t* bHiSrc = Bh + (size_t)brow * N + bn + bn4;
    const uint32_t* bLoSrc = Bl + (size_t)brow * N + bn + bn4;

    int ntiles = K2 / K2T;

    CP16(aHiDst, aHiSrc);
    CP16(aLoDst, aLoSrc);
    CP16(bHiDst, bHiSrc);
    CP16(bLoDst, bLoSrc);
    CP_COMMIT();

    for (int t = 0; t < ntiles; ++t) {
        CP_WAIT0();
        __syncthreads();

        if (t + 1 < ntiles) {
            uint32_t s = (t + 1) & 1;
            int k20 = (t + 1) * K2T;
            CP16(aHiDst + s*AS, aHiSrc + k20);
            CP16(aLoDst + s*AS, aLoSrc + k20);
            CP16(bHiDst + s*BS, bHiSrc + (size_t)k20 * N);
            CP16(bLoDst + s*BS, bLoSrc + (size_t)k20 * N);
            CP_COMMIT();
        }

        int s = t & 1;
        uint32_t ah[2][4], al[2][4];
        #pragma unroll
        for (int ma = 0; ma < 2; ++ma) {
            int r = wm*32 + ma*16 + g;
            ah[ma][0] = sAh[s][r    ][tig];   al[ma][0] = sAl[s][r    ][tig];
            ah[ma][1] = sAh[s][r + 8][tig];   al[ma][1] = sAl[s][r + 8][tig];
            ah[ma][2] = sAh[s][r    ][tig+4]; al[ma][2] = sAl[s][r    ][tig+4];
            ah[ma][3] = sAh[s][r + 8][tig+4]; al[ma][3] = sAl[s][r + 8][tig+4];
        }
        #pragma unroll
        for (int half = 0; half < 2; ++half) {
            uint32_t bh[4][2], bl[4][2];
            #pragma unroll
            for (int j = 0; j < 4; ++j) {
                int col = wn*64 + (half*4 + j)*8 + g;
                bh[j][0] = sBh[s][tig    ][col];
                bh[j][1] = sBh[s][tig + 4][col];
                bl[j][0] = sBl[s][tig    ][col];
                bl[j][1] = sBl[s][tig + 4][col];
            }
            #pragma unroll
            for (int ma = 0; ma < 2; ++ma)
                #pragma unroll
                for (int j = 0; j < 4; ++j) {
                    int nb = half*4 + j;
                    mma_bf16(c[ma][nb], ah[ma], bh[j]);
                    mma_bf16(c[ma][nb], al[ma], bh[j]);
                    mma_bf16(c[ma][nb], ah[ma], bl[j]);
                }
        }
        __syncthreads();
    }

    // epilogue
    #pragma unroll
    for (int ma = 0; ma < 2; ++ma) {
        int r0 = bm + wm*32 + ma*16 + g;
        int r1 = r0 + 8;
        #pragma unroll
        for (int nb = 0; nb < 8; ++nb) {
            int col = bn + wn*64 + nb*8 + tig*2;
            float2 o0 = make_float2(c[ma][nb][0], c[ma][nb][1]);
            float2 o1 = make_float2(c[ma][nb][2], c[ma][nb][3]);
            if (add) {
                float2 r;
                r = *(const float2*)(add + (size_t)r0*N + col);
                o0.x += r.x; o0.y += r.y;
                r = *(const float2*)(add + (size_t)r1*N + col);
                o1.x += r.x; o1.y += r.y;
            }
            *(float2*)(C + (size_t)r0*N + col) = o0;
            *(float2*)(C + (size_t)r1*N + col) = o1;
        }
    }
}

// ============================================================================
// 3xBF16 GEMM (NT): C[M,N] = A[M,K] @ E[N,K]^T  (logits). E pre-split in
// A-layout [n][k2]. No cp.async (4000 CTAs hide latency).
// ============================================================================
__global__ void __launch_bounds__(256) gemm3bf_nt(
        const uint32_t* __restrict__ Ah, const uint32_t* __restrict__ Al,
        const uint32_t* __restrict__ Eh, const uint32_t* __restrict__ El,
        float* __restrict__ C, int M, int N, int K2) {
    __shared__ uint32_t sAh[128][ASTP], sAl[128][ASTP];
    __shared__ uint32_t sBh[K2T][BSTP], sBl[K2T][BSTP];

    int tid = threadIdx.x;
    int bm = blockIdx.y * 128;
    int bn = blockIdx.x * 128;
    int w = tid >> 5, lane = tid & 31;
    int wm = w & 3, wn = w >> 2;
    int g = lane >> 2, tig = lane & 3;

    float c[2][8][4];
    #pragma unroll
    for (int i = 0; i < 2; ++i)
        #pragma unroll
        for (int j = 0; j < 8; ++j)
            #pragma unroll
            for (int q = 0; q < 4; ++q) c[i][j][q] = 0.f;

    int arow = tid >> 1, ahalf = (tid & 1) * 4;
    int ntiles = K2 / K2T;

    for (int t = 0; t < ntiles; ++t) {
        int k20 = t * K2T;
        __syncthreads();
        // A tile (16B loads)
        {
            uint4 va = *(const uint4*)(Ah + (size_t)(bm + arow) * K2 + k20 + ahalf);
            *(uint4*)(&sAh[arow][ahalf]) = va;
            uint4 vb = *(const uint4*)(Al + (size_t)(bm + arow) * K2 + k20 + ahalf);
            *(uint4*)(&sAl[arow][ahalf]) = vb;
        }
        // B tile: transpose E[n][k2] -> sB[k2][n]
        {
            uint4 ve = *(const uint4*)(Eh + (size_t)(bn + arow) * K2 + k20 + ahalf);
            sBh[ahalf+0][arow] = ve.x; sBh[ahalf+1][arow] = ve.y;
            sBh[ahalf+2][arow] = ve.z; sBh[ahalf+3][arow] = ve.w;
            uint4 vf = *(const uint4*)(El + (size_t)(bn + arow) * K2 + k20 + ahalf);
            sBl[ahalf+0][arow] = vf.x; sBl[ahalf+1][arow] = vf.y;
            sBl[ahalf+2][arow] = vf.z; sBl[ahalf+3][arow] = vf.w;
        }
        __syncthreads();

        uint32_t ah[2][4], al[2][4];
        #pragma unroll
        for (int ma = 0; ma < 2; ++ma) {
            int r = wm*32 + ma*16 + g;
            ah[ma][0] = sAh[r    ][tig];   al[ma][0] = sAl[r    ][tig];
            ah[ma][1] = sAh[r + 8][tig];   al[ma][1] = sAl[r + 8][tig];
            ah[ma][2] = sAh[r    ][tig+4]; al[ma][2] = sAl[r    ][tig+4];
            ah[ma][3] = sAh[r + 8][tig+4]; al[ma][3] = sAl[r + 8][tig+4];
        }
        #pragma unroll
        for (int half = 0; half < 2; ++half) {
            uint32_t bh[4][2], bl[4][2];
            #pragma unroll
            for (int j = 0; j < 4; ++j) {
                int col = wn*64 + (half*4 + j)*8 + g;
                bh[j][0] = sBh[tig    ][col];
                bh[j][1] = sBh[tig + 4][col];
                bl[j][0] = sBl[tig    ][col];
                bl[j][1] = sBl[tig + 4][col];
            }
            #pragma unroll
            for (int ma = 0; ma < 2; ++ma)
                #pragma unroll
                for (int j = 0; j < 4; ++j) {
                    int nb = half*4 + j;
                    mma_bf16(c[ma][nb], ah[ma], bh[j]);
                    mma_bf16(c[ma][nb], al[ma], bh[j]);
                    mma_bf16(c[ma][nb], ah[ma], bl[j]);
                }
        }
    }

    #pragma unroll
    for (int ma = 0; ma < 2; ++ma) {
        int r0 = bm + wm*32 + ma*16 + g;
        int r1 = r0 + 8;
        #pragma unroll
        for (int nb = 0; nb < 8; ++nb) {
            int col = bn + wn*64 + nb*8 + tig*2;
            *(float2*)(C + (size_t)r0*N + col) = make_float2(c[ma][nb][0], c[ma][nb][1]);
            *(float2*)(C + (size_t)r1*N + col) = make_float2(c[ma][nb][2], c[ma][nb][3]);
        }
    }
}

// ---------------- RoPE (in-place on packed qkv) -----------------------------
__global__ void rope_k(float* __restrict__ x, int rowstride) {
    int m = blockIdx.x;
    int h = blockIdx.y;
    int s = m % SEQ;
    int j = threadIdx.x;  // 0..31
    float* p = x + (size_t)m * rowstride + h * HD;
    float invf = expf(-(2.0f * j / 64.0f) * 9.210340371976184f);
    float ang = (float)s * invf;
    float cc, sn;
    sincosf(ang, &sn, &cc);
    float x1 = p[j], x2 = p[j + 32];
    p[j]      = x1 * cc - x2 * sn;
    p[j + 32] = x2 * cc + x1 * sn;
}

// ---------------- attention (qkv packed rows of 1536) -----------------------
__global__ void __launch_bounds__(128) attn_k(
        const float* __restrict__ qkv, float* __restrict__ out) {
    int sq = blockIdx.x, h = blockIdx.y, b = blockIdx.z;
    int kvh = h >> 2;                       // NREP = 4
    int tid = threadIdx.x;                  // 128
    __shared__ float qs[HD];
    __shared__ float sc[SEQ];
    __shared__ float red[128];

    const float* qrow = qkv + (size_t)(b*SEQ + sq) * QKVN + h * HD;
    if (tid < HD) qs[tid] = qrow[tid];
    __syncthreads();

    int nk = sq + 1;
    float lmax = -1e30f;
    for (int j = tid; j < nk; j += 128) {
        const float* kr = qkv + (size_t)(b*SEQ + j) * QKVN + 1024 + kvh * HD;
        float d = 0.f;
        #pragma unroll
        for (int t = 0; t < 16; ++t) {
            float4 kk = *(const float4*)(kr + t*4);
            float4 qq = *(const float4*)(qs + t*4);
            d += kk.x*qq.x + kk.y*qq.y + kk.z*qq.z + kk.w*qq.w;
        }
        d *= 0.125f;
        sc[j] = d;
        lmax = fmaxf(lmax, d);
    }
    red[tid] = lmax; __syncthreads();
    for (int s = 64; s > 0; s >>= 1) {
        if (tid < s) red[tid] = fmaxf(red[tid], red[tid + s]);
        __syncthreads();
    }
    float mx = red[0];
    __syncthreads();

    float lsum = 0.f;
    for (int j = tid; j < nk; j += 128) {
        float p = expf(sc[j] - mx);
        sc[j] = p;
        lsum += p;
    }
    red[tid] = lsum; __syncthreads();
    for (int s = 64; s > 0; s >>= 1) {
        if (tid < s) red[tid] += red[tid + s];
        __syncthreads();
    }
    float inv = 1.0f / red[0];
    __syncthreads();

    int d = tid & 63, part = tid >> 6;
    float acc = 0.f;
    for (int j = part; j < nk; j += 2) {
        acc += sc[j] * qkv[(size_t)(b*SEQ + j) * QKVN + 1280 + kvh * HD + d];
    }
    red[tid] = acc; __syncthreads();
    if (tid < 64)
        out[(size_t)(b*SEQ + sq) * DIM + h * HD + tid] = (red[tid] + red[tid + 64]) * inv;
}

// ---------------- silu(gate)*up -> split bf16 hi/lo -------------------------
// gu: [NTOK][8192] fp32, gate cols 0..4095, up cols 4096..8191
__global__ void silu_mul_split_k(const float* __restrict__ gu,
                                 uint32_t* __restrict__ dh, uint32_t* __restrict__ dl,
                                 int n2) {
    int i = blockIdx.x * 256 + threadIdx.x;
    if (i >= n2) return;
    int row = i / (FFD/2);
    int c2  = i - row * (FFD/2);
    const float* base = gu + (size_t)row * GUN;
    float2 g = *(const float2*)(base + c2*2);
    float2 u = *(const float2*)(base + FFD + c2*2);
    float y0 = (g.x / (1.0f + expf(-g.x))) * u.x;
    float y1 = (g.y / (1.0f + expf(-g.y))) * u.y;
    uint32_t hi, lo;
    split2(y0, y1, hi, lo);
    dh[i] = hi; dl[i] = lo;
}

// ---------------- host orchestration ----------------------------------------
extern "C" void kernel_launch(void* const* d_in, const int* in_sizes, int n_in,
                              void* d_out, int out_size) {
    const int*   tokens  = (const int*)  d_in[0];
    const float* embed   = (const float*)d_in[1];
    const float* wq      = (const float*)d_in[2];
    const float* wk      = (const float*)d_in[3];
    const float* wv      = (const float*)d_in[4];
    const float* wo      = (const float*)d_in[5];
    const float* w_gate  = (const float*)d_in[6];
    const float* w_up    = (const float*)d_in[7];
    const float* w_down  = (const float*)d_in[8];
    const float* norm1_w = (const float*)d_in[9];
    const float* norm2_w = (const float*)d_in[10];
    const float* fnorm_w = (const float*)d_in[11];
    float* logits = (float*)d_out;

    float *x, *qkv, *ao, *gu;
    uint32_t *hh, *hl, *aoh, *aol, *ffh, *ffl;
    uint32_t *wqkvh, *wqkvl, *woh, *wol, *wguh, *wgul, *wdh, *wdl, *embh, *embl;
    cudaGetSymbolAddress((void**)&x,    g_x);
    cudaGetSymbolAddress((void**)&qkv,  g_qkv);
    cudaGetSymbolAddress((void**)&ao,   g_ao);
    cudaGetSymbolAddress((void**)&gu,   g_gu);
    cudaGetSymbolAddress((void**)&hh,   g_hh);
    cudaGetSymbolAddress((void**)&hl,   g_hl);
    cudaGetSymbolAddress((void**)&aoh,  g_aoh);
    cudaGetSymbolAddress((void**)&aol,  g_aol);
    cudaGetSymbolAddress((void**)&ffh,  g_ffh);
    cudaGetSymbolAddress((void**)&ffl,  g_ffl);
    cudaGetSymbolAddress((void**)&wqkvh, g_wqkvh);
    cudaGetSymbolAddress((void**)&wqkvl, g_wqkvl);
    cudaGetSymbolAddress((void**)&woh,  g_woh);
    cudaGetSymbolAddress((void**)&wol,  g_wol);
    cudaGetSymbolAddress((void**)&wguh, g_wguh);
    cudaGetSymbolAddress((void**)&wgul, g_wgul);
    cudaGetSymbolAddress((void**)&wdh,  g_wdh);
    cudaGetSymbolAddress((void**)&wdl,  g_wdl);
    cudaGetSymbolAddress((void**)&embh, g_embh);
    cudaGetSymbolAddress((void**)&embl, g_embl);

    const int K2D = DIM/2;   // 512
    const int K2F = FFD/2;   // 2048

    // ---- weight split (per call; weights may differ call to call) ----
    for (int i = 0; i < NL; ++i) {
        size_t qkvOff = (size_t)i * K2D * QKVN;
        split_B<<<(K2D*1024+255)/256, 256>>>(wq + (size_t)i*DIM*DIM,
            wqkvh + qkvOff, wqkvl + qkvOff, K2D, 1024, QKVN);
        split_B<<<(K2D*256+255)/256, 256>>>(wk + (size_t)i*DIM*256,
            wqkvh + qkvOff + 1024, wqkvl + qkvOff + 1024, K2D, 256, QKVN);
        split_B<<<(K2D*256+255)/256, 256>>>(wv + (size_t)i*DIM*256,
            wqkvh + qkvOff + 1280, wqkvl + qkvOff + 1280, K2D, 256, QKVN);
        size_t woOff = (size_t)i * K2D * DIM;
        split_B<<<(K2D*DIM+255)/256, 256>>>(wo + (size_t)i*DIM*DIM,
            woh + woOff, wol + woOff, K2D, DIM, DIM);
        size_t guOff = (size_t)i * K2D * GUN;
        split_B<<<(K2D*FFD+255)/256, 256>>>(w_gate + (size_t)i*DIM*FFD,
            wguh + guOff, wgul + guOff, K2D, FFD, GUN);
        split_B<<<(K2D*FFD+255)/256, 256>>>(w_up + (size_t)i*DIM*FFD,
            wguh + guOff + FFD, wgul + guOff + FFD, K2D, FFD, GUN);
        size_t wdOff = (size_t)i * K2F * DIM;
        split_B<<<(K2F*DIM+255)/256, 256>>>(w_down + (size_t)i*FFD*DIM,
            wdh + wdOff, wdl + wdOff, K2F, DIM, DIM);
    }
    split_A<<<(VOCAB*K2D+255)/256, 256>>>(embed, embh, embl, VOCAB*K2D);

    embed_k<<<NTOK, 256>>>(tokens, embed, x);

    dim3 g_qkvG(QKVN/128, NTOK/128);  // (12, 16)
    dim3 g_dG(DIM/128,    NTOK/128);  // (8, 16)
    dim3 g_guG(GUN/128,   NTOK/128);  // (64, 16)
    dim3 g_lgG(VOCAB/128, NTOK/128);  // (250, 16)

    for (int i = 0; i < NL; ++i) {
        size_t qkvOff = (size_t)i * K2D * QKVN;
        size_t woOff  = (size_t)i * K2D * DIM;
        size_t guOff  = (size_t)i * K2D * GUN;
        size_t wdOff  = (size_t)i * K2F * DIM;

        rmsnorm_split_k<<<NTOK, 256>>>(x, norm1_w + (size_t)i*DIM, hh, hl);

        gemm3bf_nn<<<g_qkvG, 256>>>(hh, hl, wqkvh + qkvOff, wqkvl + qkvOff,
                                    nullptr, qkv, NTOK, QKVN, K2D);

        rope_k<<<dim3(NTOK, NH), 32>>>(qkv, QKVN);
        rope_k<<<dim3(NTOK, NKV), 32>>>(qkv + 1024, QKVN);

        attn_k<<<dim3(SEQ, NH, BATCH), 128>>>(qkv, ao);
        split_A<<<(NTOK*K2D+255)/256, 256>>>(ao, aoh, aol, NTOK*K2D);

        gemm3bf_nn<<<g_dG, 256>>>(aoh, aol, woh + woOff, wol + woOff,
                                  x, x, NTOK, DIM, K2D);

        rmsnorm_split_k<<<NTOK, 256>>>(x, norm2_w + (size_t)i*DIM, hh, hl);

        gemm3bf_nn<<<g_guG, 256>>>(hh, hl, wguh + guOff, wgul + guOff,
                                   nullptr, gu, NTOK, GUN, K2D);

        silu_mul_split_k<<<(NTOK*K2F+255)/256, 256>>>(gu, ffh, ffl, NTOK*K2F);

        gemm3bf_nn<<<g_dG, 256>>>(ffh, ffl, wdh + wdOff, wdl + wdOff,
                                  x, x, NTOK, DIM, K2F);
    }

    rmsnorm_split_k<<<NTOK, 256>>>(x, fnorm_w, hh, hl);
    gemm3bf_nt<<<g_lgG, 256>>>(hh, hl, embh, embl, logits, NTOK, VOCAB, K2D);
}

// round 10
// speedup vs baseline: 1.7283x; 1.1105x over previous
#include <cuda_runtime.h>
#include <cuda_bf16.h>
#include <math.h>
#include <stdint.h>

// Model dims
#define VOCAB 32000
#define DIM   1024
#define NH    16
#define NKV   4
#define FFD   4096
#define NL    8
#define HD    64
#define BATCH 2
#define SEQ   1024
#define NTOK  (BATCH*SEQ)   // 2048
#define QKVN  1536          // 1024 q + 256 k + 256 v
#define GUN   8192          // gate | up

// ---------------- scratch (device globals; no allocation allowed) ----------
__device__ float g_x[NTOK*DIM];
__device__ float g_qkv[NTOK*QKVN];
__device__ float g_ao[NTOK*DIM];
__device__ float g_gu[NTOK*GUN];

// split activations (packed bf16 hi/lo pairs along k; u32 per pair)
__device__ uint32_t g_hh[NTOK*DIM/2],  g_hl[NTOK*DIM/2];
__device__ uint32_t g_aoh[NTOK*DIM/2], g_aol[NTOK*DIM/2];
__device__ uint32_t g_ffh[NTOK*FFD/2], g_ffl[NTOK*FFD/2];

// split weights (B layout: [k2][n], pair along k)
__device__ uint32_t g_wqkvh[NL*(DIM/2)*QKVN], g_wqkvl[NL*(DIM/2)*QKVN];
__device__ uint32_t g_woh[NL*(DIM/2)*DIM],    g_wol[NL*(DIM/2)*DIM];
__device__ uint32_t g_wguh[NL*(DIM/2)*GUN],   g_wgul[NL*(DIM/2)*GUN];
__device__ uint32_t g_wdh[NL*(FFD/2)*DIM],    g_wdl[NL*(FFD/2)*DIM];
// embed transposed+split to B layout [k2][VOCAB]
__device__ uint32_t g_embBh[(DIM/2)*VOCAB], g_embBl[(DIM/2)*VOCAB];

// ---------------- helpers ---------------------------------------------------
__device__ __forceinline__ void split2(float x0, float x1, uint32_t& hi, uint32_t& lo) {
    __nv_bfloat16 h0 = __float2bfloat16_rn(x0);
    __nv_bfloat16 h1 = __float2bfloat16_rn(x1);
    __nv_bfloat16 l0 = __float2bfloat16_rn(x0 - __bfloat162float(h0));
    __nv_bfloat16 l1 = __float2bfloat16_rn(x1 - __bfloat162float(h1));
    hi = ((uint32_t)__bfloat16_as_ushort(h1) << 16) | __bfloat16_as_ushort(h0);
    lo = ((uint32_t)__bfloat16_as_ushort(l1) << 16) | __bfloat16_as_ushort(l0);
}

#define CP16(dst, src) asm volatile("cp.async.cg.shared.global [%0], [%1], 16;\n" :: "r"(dst), "l"(src))
#define CP_COMMIT()    asm volatile("cp.async.commit_group;\n")
#define CP_WAIT0()     asm volatile("cp.async.wait_group 0;\n")

__device__ __forceinline__ void mma_bf16(float c[4], const uint32_t a[4], const uint32_t b[2]) {
    asm volatile(
        "mma.sync.aligned.m16n8k16.row.col.f32.bf16.bf16.f32 "
        "{%0,%1,%2,%3}, {%4,%5,%6,%7}, {%8,%9}, {%0,%1,%2,%3};\n"
        : "+f"(c[0]), "+f"(c[1]), "+f"(c[2]), "+f"(c[3])
        : "r"(a[0]), "r"(a[1]), "r"(a[2]), "r"(a[3]), "r"(b[0]), "r"(b[1]));
}

// ---------------- weight split kernels --------------------------------------
// B layout: dst[k2][ldDst] = pack(src[2k2][n], src[2k2+1][n])
__global__ void split_B(const float* __restrict__ src, uint32_t* __restrict__ dh,
                        uint32_t* __restrict__ dl, int K2, int N, int ldDst) {
    int idx = blockIdx.x * 256 + threadIdx.x;
    if (idx >= K2 * N) return;
    int k2 = idx / N, n = idx - k2 * N;
    float x0 = src[(size_t)(2*k2)   * N + n];
    float x1 = src[(size_t)(2*k2+1) * N + n];
    uint32_t hi, lo;
    split2(x0, x1, hi, lo);
    dh[(size_t)k2 * ldDst + n] = hi;
    dl[(size_t)k2 * ldDst + n] = lo;
}

// Transpose+split embed: src [N][2*K2] -> dst [k2][N]
__global__ void split_Et(const float* __restrict__ src, uint32_t* __restrict__ dh,
                         uint32_t* __restrict__ dl, int K2, int N) {
    __shared__ uint32_t sh[32][33], sl[32][33];
    int n0 = blockIdx.x * 32, k20 = blockIdx.y * 32;
    int tx = threadIdx.x, ty = threadIdx.y;  // 32 x 8
    #pragma unroll
    for (int i = 0; i < 4; ++i) {
        int nn = i * 8 + ty;
        float2 x = *(const float2*)(src + (size_t)(n0 + nn) * (2*K2) + 2*(k20 + tx));
        uint32_t hi, lo;
        split2(x.x, x.y, hi, lo);
        sh[nn][tx] = hi; sl[nn][tx] = lo;   // [n][k2]
    }
    __syncthreads();
    #pragma unroll
    for (int i = 0; i < 4; ++i) {
        int kk = i * 8 + ty;
        size_t o = (size_t)(k20 + kk) * N + n0 + tx;
        dh[o] = sh[tx][kk];
        dl[o] = sl[tx][kk];
    }
}

// A-layout split: dst[i] = pack(src[2i], src[2i+1])  (contiguous)
__global__ void split_A(const float* __restrict__ src, uint32_t* __restrict__ dh,
                        uint32_t* __restrict__ dl, int n2) {
    int i = blockIdx.x * 256 + threadIdx.x;
    if (i >= n2) return;
    float2 x = ((const float2*)src)[i];
    uint32_t hi, lo;
    split2(x.x, x.y, hi, lo);
    dh[i] = hi; dl[i] = lo;
}

// ---------------- embedding gather ------------------------------------------
__global__ void embed_k(const int* __restrict__ tok, const float* __restrict__ emb,
                        float* __restrict__ x) {
    int m = blockIdx.x;
    int t = tok[m];
    const float4* src = (const float4*)(emb + (size_t)t * DIM);
    float4* dst = (float4*)(x + (size_t)m * DIM);
    dst[threadIdx.x] = src[threadIdx.x];
}

// ---------------- rmsnorm -> split bf16 hi/lo -------------------------------
__global__ void rmsnorm_split_k(const float* __restrict__ x, const float* __restrict__ w,
                                uint32_t* __restrict__ dh, uint32_t* __restrict__ dl) {
    int m = blockIdx.x;
    int tid = threadIdx.x;  // 256
    const float4* xr = (const float4*)(x + (size_t)m * DIM);
    float4 v = xr[tid];
    float ss = v.x*v.x + v.y*v.y + v.z*v.z + v.w*v.w;
    __shared__ float red[256];
    red[tid] = ss; __syncthreads();
    for (int s = 128; s > 0; s >>= 1) {
        if (tid < s) red[tid] += red[tid + s];
        __syncthreads();
    }
    float scale = rsqrtf(red[0] * (1.0f/DIM) + 1e-6f);
    float4 wv = ((const float4*)w)[tid];
    float o0 = v.x*scale*wv.x, o1 = v.y*scale*wv.y;
    float o2 = v.z*scale*wv.z, o3 = v.w*scale*wv.w;
    uint32_t h0, l0, h1, l1;
    split2(o0, o1, h0, l0);
    split2(o2, o3, h1, l1);
    size_t base = (size_t)m * (DIM/2) + tid*2;
    dh[base] = h0; dh[base+1] = h1;
    dl[base] = l0; dl[base+1] = l1;
}

// ============================================================================
// 3xBF16 tensor-core GEMM (NN): C[M,N] = A[M,K] @ B[K,N] (+ add)
// A pre-split: Ah/Al [M][K2] u32 (pair along k). B pre-split: Bh/Bl [K2][N].
// BM=128 BN=128 K-tile 32 bf16 (K2T=16), 256 threads, 8 warps (4M x 2N),
// warp tile 32x64. cp.async 2-stage pipeline (dynamic smem, 2 CTAs/SM).
// ============================================================================
#define K2T 16
#define ASTP 20     // A smem row stride (u32)
#define BSTP 136    // B smem row stride (u32); 136 mod 32 = 8 -> conflict-free
#define A_ST_B (128*ASTP*4)     // 10240 bytes per A array stage
#define B_ST_B (K2T*BSTP*4)     // 8704 bytes per B array stage
#define OFF_AH 0
#define OFF_AL (2*A_ST_B)               // 20480
#define OFF_BH (4*A_ST_B)               // 40960
#define OFF_BL (OFF_BH + 2*B_ST_B)      // 58368
#define GSMEM  (OFF_BL + 2*B_ST_B)      // 75776 bytes

__global__ void __launch_bounds__(256, 2) gemm3bf_nn(
        const uint32_t* __restrict__ Ah, const uint32_t* __restrict__ Al,
        const uint32_t* __restrict__ Bh, const uint32_t* __restrict__ Bl,
        const float* __restrict__ add, float* __restrict__ C,
        int M, int N, int K2) {
    extern __shared__ char smem[];
    int tid = threadIdx.x;
    int bm = blockIdx.y * 128;
    int bn = blockIdx.x * 128;
    int w = tid >> 5, lane = tid & 31;
    int wm = w & 3, wn = w >> 2;
    int g = lane >> 2, tig = lane & 3;

    uint32_t aHiB, aLoB, bHiB, bLoB;
    {
        uint32_t sb;
        asm("{ .reg .u64 t; cvta.to.shared.u64 t, %1; cvt.u32.u64 %0, t; }" : "=r"(sb) : "l"(smem));
        aHiB = sb + OFF_AH; aLoB = sb + OFF_AL;
        bHiB = sb + OFF_BH; bLoB = sb + OFF_BL;
    }

    float c[2][8][4];
    #pragma unroll
    for (int i = 0; i < 2; ++i)
        #pragma unroll
        for (int j = 0; j < 8; ++j)
            #pragma unroll
            for (int q = 0; q < 4; ++q) c[i][j][q] = 0.f;

    int ntiles = K2 / K2T;

    auto fill = [&](int stage, int k2o) {
        uint32_t ao = stage ? A_ST_B : 0;
        uint32_t bo = stage ? B_ST_B : 0;
        #pragma unroll
        for (int i = 0; i < 2; ++i) {
            int ch = tid + i * 256;               // 0..511
            int arow = ch >> 2, ac4 = (ch & 3) << 2;
            uint32_t ad = (uint32_t)((arow * ASTP + ac4) * 4);
            size_t asrc = (size_t)(bm + arow) * K2 + k2o + ac4;
            CP16(aHiB + ao + ad, Ah + asrc);
            CP16(aLoB + ao + ad, Al + asrc);
            int brow = ch >> 5, bn4 = (ch & 31) << 2;
            uint32_t bd = (uint32_t)((brow * BSTP + bn4) * 4);
            size_t bsrc = (size_t)(k2o + brow) * N + bn + bn4;
            CP16(bHiB + bo + bd, Bh + bsrc);
            CP16(bLoB + bo + bd, Bl + bsrc);
        }
        CP_COMMIT();
    };

    fill(0, 0);

    for (int t = 0; t < ntiles; ++t) {
        CP_WAIT0();
        __syncthreads();

        if (t + 1 < ntiles) fill((t + 1) & 1, (t + 1) * K2T);

        int s = t & 1;
        const uint32_t* pAh = (const uint32_t*)(smem + OFF_AH + (s ? A_ST_B : 0));
        const uint32_t* pAl = (const uint32_t*)(smem + OFF_AL + (s ? A_ST_B : 0));
        const uint32_t* pBh = (const uint32_t*)(smem + OFF_BH + (s ? B_ST_B : 0));
        const uint32_t* pBl = (const uint32_t*)(smem + OFF_BL + (s ? B_ST_B : 0));

        #pragma unroll
        for (int kk = 0; kk < K2T; kk += 8) {
            uint32_t ah[2][4], al[2][4];
            #pragma unroll
            for (int ma = 0; ma < 2; ++ma) {
                int r = wm*32 + ma*16 + g;
                ah[ma][0] = pAh[r*ASTP + kk + tig];
                ah[ma][1] = pAh[(r+8)*ASTP + kk + tig];
                ah[ma][2] = pAh[r*ASTP + kk + tig + 4];
                ah[ma][3] = pAh[(r+8)*ASTP + kk + tig + 4];
                al[ma][0] = pAl[r*ASTP + kk + tig];
                al[ma][1] = pAl[(r+8)*ASTP + kk + tig];
                al[ma][2] = pAl[r*ASTP + kk + tig + 4];
                al[ma][3] = pAl[(r+8)*ASTP + kk + tig + 4];
            }
            #pragma unroll
            for (int half = 0; half < 2; ++half) {
                uint32_t bh[4][2], bl[4][2];
                #pragma unroll
                for (int j = 0; j < 4; ++j) {
                    int col = wn*64 + (half*4 + j)*8 + g;
                    bh[j][0] = pBh[(kk + tig)*BSTP + col];
                    bh[j][1] = pBh[(kk + tig + 4)*BSTP + col];
                    bl[j][0] = pBl[(kk + tig)*BSTP + col];
                    bl[j][1] = pBl[(kk + tig + 4)*BSTP + col];
                }
                #pragma unroll
                for (int ma = 0; ma < 2; ++ma)
                    #pragma unroll
                    for (int j = 0; j < 4; ++j) {
                        int nb = half*4 + j;
                        mma_bf16(c[ma][nb], ah[ma], bh[j]);
                        mma_bf16(c[ma][nb], al[ma], bh[j]);
                        mma_bf16(c[ma][nb], ah[ma], bl[j]);
                    }
            }
        }
        __syncthreads();
    }

    // epilogue
    #pragma unroll
    for (int ma = 0; ma < 2; ++ma) {
        int r0 = bm + wm*32 + ma*16 + g;
        int r1 = r0 + 8;
        #pragma unroll
        for (int nb = 0; nb < 8; ++nb) {
            int col = bn + wn*64 + nb*8 + tig*2;
            float2 o0 = make_float2(c[ma][nb][0], c[ma][nb][1]);
            float2 o1 = make_float2(c[ma][nb][2], c[ma][nb][3]);
            if (add) {
                float2 r;
                r = *(const float2*)(add + (size_t)r0*N + col);
                o0.x += r.x; o0.y += r.y;
                r = *(const float2*)(add + (size_t)r1*N + col);
                o1.x += r.x; o1.y += r.y;
            }
            *(float2*)(C + (size_t)r0*N + col) = o0;
            *(float2*)(C + (size_t)r1*N + col) = o1;
        }
    }
}

// ---------------- RoPE (in-place on packed qkv) -----------------------------
__global__ void rope_k(float* __restrict__ x, int rowstride) {
    int m = blockIdx.x;
    int h = blockIdx.y;
    int s = m % SEQ;
    int j = threadIdx.x;  // 0..31
    float* p = x + (size_t)m * rowstride + h * HD;
    float invf = expf(-(2.0f * j / 64.0f) * 9.210340371976184f);
    float ang = (float)s * invf;
    float cc, sn;
    sincosf(ang, &sn, &cc);
    float x1 = p[j], x2 = p[j + 32];
    p[j]      = x1 * cc - x2 * sn;
    p[j + 32] = x2 * cc + x1 * sn;
}

// ---------------- attention (qkv packed rows of 1536) -----------------------
__global__ void __launch_bounds__(128) attn_k(
        const float* __restrict__ qkv, float* __restrict__ out) {
    int sq = blockIdx.x, h = blockIdx.y, b = blockIdx.z;
    int kvh = h >> 2;                       // NREP = 4
    int tid = threadIdx.x;                  // 128
    __shared__ float qs[HD];
    __shared__ float sc[SEQ];
    __shared__ float red[128];

    const float* qrow = qkv + (size_t)(b*SEQ + sq) * QKVN + h * HD;
    if (tid < HD) qs[tid] = qrow[tid];
    __syncthreads();

    int nk = sq + 1;
    float lmax = -1e30f;
    for (int j = tid; j < nk; j += 128) {
        const float* kr = qkv + (size_t)(b*SEQ + j) * QKVN + 1024 + kvh * HD;
        float d = 0.f;
        #pragma unroll
        for (int t = 0; t < 16; ++t) {
            float4 kk = *(const float4*)(kr + t*4);
            float4 qq = *(const float4*)(qs + t*4);
            d += kk.x*qq.x + kk.y*qq.y + kk.z*qq.z + kk.w*qq.w;
        }
        d *= 0.125f;
        sc[j] = d;
        lmax = fmaxf(lmax, d);
    }
    red[tid] = lmax; __syncthreads();
    for (int s = 64; s > 0; s >>= 1) {
        if (tid < s) red[tid] = fmaxf(red[tid], red[tid + s]);
        __syncthreads();
    }
    float mx = red[0];
    __syncthreads();

    float lsum = 0.f;
    for (int j = tid; j < nk; j += 128) {
        float p = __expf(sc[j] - mx);
        sc[j] = p;
        lsum += p;
    }
    red[tid] = lsum; __syncthreads();
    for (int s = 64; s > 0; s >>= 1) {
        if (tid < s) red[tid] += red[tid + s];
        __syncthreads();
    }
    float inv = 1.0f / red[0];
    __syncthreads();

    int d = tid & 63, part = tid >> 6;
    float acc = 0.f;
    for (int j = part; j < nk; j += 2) {
        acc += sc[j] * qkv[(size_t)(b*SEQ + j) * QKVN + 1280 + kvh * HD + d];
    }
    red[tid] = acc; __syncthreads();
    if (tid < 64)
        out[(size_t)(b*SEQ + sq) * DIM + h * HD + tid] = (red[tid] + red[tid + 64]) * inv;
}

// ---------------- silu(gate)*up -> split bf16 hi/lo -------------------------
__global__ void silu_mul_split_k(const float* __restrict__ gu,
                                 uint32_t* __restrict__ dh, uint32_t* __restrict__ dl,
                                 int n2) {
    int i = blockIdx.x * 256 + threadIdx.x;
    if (i >= n2) return;
    int row = i / (FFD/2);
    int c2  = i - row * (FFD/2);
    const float* base = gu + (size_t)row * GUN;
    float2 g = *(const float2*)(base + c2*2);
    float2 u = *(const float2*)(base + FFD + c2*2);
    float y0 = (g.x / (1.0f + __expf(-g.x))) * u.x;
    float y1 = (g.y / (1.0f + __expf(-g.y))) * u.y;
    uint32_t hi, lo;
    split2(y0, y1, hi, lo);
    dh[i] = hi; dl[i] = lo;
}

// ---------------- host orchestration ----------------------------------------
extern "C" void kernel_launch(void* const* d_in, const int* in_sizes, int n_in,
                              void* d_out, int out_size) {
    const int*   tokens  = (const int*)  d_in[0];
    const float* embed   = (const float*)d_in[1];
    const float* wq      = (const float*)d_in[2];
    const float* wk      = (const float*)d_in[3];
    const float* wv      = (const float*)d_in[4];
    const float* wo      = (const float*)d_in[5];
    const float* w_gate  = (const float*)d_in[6];
    const float* w_up    = (const float*)d_in[7];
    const float* w_down  = (const float*)d_in[8];
    const float* norm1_w = (const float*)d_in[9];
    const float* norm2_w = (const float*)d_in[10];
    const float* fnorm_w = (const float*)d_in[11];
    float* logits = (float*)d_out;

    float *x, *qkv, *ao, *gu;
    uint32_t *hh, *hl, *aoh, *aol, *ffh, *ffl;
    uint32_t *wqkvh, *wqkvl, *woh, *wol, *wguh, *wgul, *wdh, *wdl, *embBh, *embBl;
    cudaGetSymbolAddress((void**)&x,    g_x);
    cudaGetSymbolAddress((void**)&qkv,  g_qkv);
    cudaGetSymbolAddress((void**)&ao,   g_ao);
    cudaGetSymbolAddress((void**)&gu,   g_gu);
    cudaGetSymbolAddress((void**)&hh,   g_hh);
    cudaGetSymbolAddress((void**)&hl,   g_hl);
    cudaGetSymbolAddress((void**)&aoh,  g_aoh);
    cudaGetSymbolAddress((void**)&aol,  g_aol);
    cudaGetSymbolAddress((void**)&ffh,  g_ffh);
    cudaGetSymbolAddress((void**)&ffl,  g_ffl);
    cudaGetSymbolAddress((void**)&wqkvh, g_wqkvh);
    cudaGetSymbolAddress((void**)&wqkvl, g_wqkvl);
    cudaGetSymbolAddress((void**)&woh,  g_woh);
    cudaGetSymbolAddress((void**)&wol,  g_wol);
    cudaGetSymbolAddress((void**)&wguh, g_wguh);
    cudaGetSymbolAddress((void**)&wgul, g_wgul);
    cudaGetSymbolAddress((void**)&wdh,  g_wdh);
    cudaGetSymbolAddress((void**)&wdl,  g_wdl);
    cudaGetSymbolAddress((void**)&embBh, g_embBh);
    cudaGetSymbolAddress((void**)&embBl, g_embBl);

    cudaFuncSetAttribute(gemm3bf_nn, cudaFuncAttributeMaxDynamicSharedMemorySize, GSMEM);

    const int K2D = DIM/2;   // 512
    const int K2F = FFD/2;   // 2048

    // ---- weight split (per call; weights may differ call to call) ----
    for (int i = 0; i < NL; ++i) {
        size_t qkvOff = (size_t)i * K2D * QKVN;
        split_B<<<(K2D*1024+255)/256, 256>>>(wq + (size_t)i*DIM*DIM,
            wqkvh + qkvOff, wqkvl + qkvOff, K2D, 1024, QKVN);
        split_B<<<(K2D*256+255)/256, 256>>>(wk + (size_t)i*DIM*256,
            wqkvh + qkvOff + 1024, wqkvl + qkvOff + 1024, K2D, 256, QKVN);
        split_B<<<(K2D*256+255)/256, 256>>>(wv + (size_t)i*DIM*256,
            wqkvh + qkvOff + 1280, wqkvl + qkvOff + 1280, K2D, 256, QKVN);
        size_t woOff = (size_t)i * K2D * DIM;
        split_B<<<(K2D*DIM+255)/256, 256>>>(wo + (size_t)i*DIM*DIM,
            woh + woOff, wol + woOff, K2D, DIM, DIM);
        size_t guOff = (size_t)i * K2D * GUN;
        split_B<<<(K2D*FFD+255)/256, 256>>>(w_gate + (size_t)i*DIM*FFD,
            wguh + guOff, wgul + guOff, K2D, FFD, GUN);
        split_B<<<(K2D*FFD+255)/256, 256>>>(w_up + (size_t)i*DIM*FFD,
            wguh + guOff + FFD, wgul + guOff + FFD, K2D, FFD, GUN);
        size_t wdOff = (size_t)i * K2F * DIM;
        split_B<<<(K2F*DIM+255)/256, 256>>>(w_down + (size_t)i*FFD*DIM,
            wdh + wdOff, wdl + wdOff, K2F, DIM, DIM);
    }
    split_Et<<<dim3(VOCAB/32, K2D/32), dim3(32, 8)>>>(embed, embBh, embBl, K2D, VOCAB);

    embed_k<<<NTOK, 256>>>(tokens, embed, x);

    dim3 g_qkvG(QKVN/128, NTOK/128);  // (12, 16)
    dim3 g_dG(DIM/128,    NTOK/128);  // (8, 16)
    dim3 g_guG(GUN/128,   NTOK/128);  // (64, 16)
    dim3 g_lgG(VOCAB/128, NTOK/128);  // (250, 16)

    for (int i = 0; i < NL; ++i) {
        size_t qkvOff = (size_t)i * K2D * QKVN;
        size_t woOff  = (size_t)i * K2D * DIM;
        size_t guOff  = (size_t)i * K2D * GUN;
        size_t wdOff  = (size_t)i * K2F * DIM;

        rmsnorm_split_k<<<NTOK, 256>>>(x, norm1_w + (size_t)i*DIM, hh, hl);

        gemm3bf_nn<<<g_qkvG, 256, GSMEM>>>(hh, hl, wqkvh + qkvOff, wqkvl + qkvOff,
                                           nullptr, qkv, NTOK, QKVN, K2D);

        rope_k<<<dim3(NTOK, NH), 32>>>(qkv, QKVN);
        rope_k<<<dim3(NTOK, NKV), 32>>>(qkv + 1024, QKVN);

        attn_k<<<dim3(SEQ, NH, BATCH), 128>>>(qkv, ao);
        split_A<<<(NTOK*K2D+255)/256, 256>>>(ao, aoh, aol, NTOK*K2D);

        gemm3bf_nn<<<g_dG, 256, GSMEM>>>(aoh, aol, woh + woOff, wol + woOff,
                                         x, x, NTOK, DIM, K2D);

        rmsnorm_split_k<<<NTOK, 256>>>(x, norm2_w + (size_t)i*DIM, hh, hl);

        gemm3bf_nn<<<g_guG, 256, GSMEM>>>(hh, hl, wguh + guOff, wgul + guOff,
                                          nullptr, gu, NTOK, GUN, K2D);

        silu_mul_split_k<<<(NTOK*K2F+255)/256, 256>>>(gu, ffh, ffl, NTOK*K2F);

        gemm3bf_nn<<<g_dG, 256, GSMEM>>>(ffh, ffl, wdh + wdOff, wdl + wdOff,
                                         x, x, NTOK, DIM, K2F);
    }

    rmsnorm_split_k<<<NTOK, 256>>>(x, fnorm_w, hh, hl);
    gemm3bf_nn<<<g_lgG, 256, GSMEM>>>(hh, hl, embBh, embBl, nullptr, logits,
                                      NTOK, VOCAB, K2D);
}